// round 16
// baseline (speedup 1.0000x reference)
#include <cuda_runtime.h>
#include <math.h>

// Problem constants
#define P_TOT   16200   // H*W
#define MD      130
#define L       128
#define NH      8
#define S       16
#define K       25
#define NNB     25
#define MH      32
#define FH      256

typedef unsigned long long u64;

// Scratch (allocation-free: __device__ globals)
__device__ __align__(16) float g_xL  [P_TOT * L];        // packed x[:, :128]
__device__ __align__(16) float g_wp  [P_TOT * NNB * S];  // precomputed W2
__device__ __align__(16) float g_xmix[P_TOT * L];        // x_mix

// packed f32x2 ops (sm_103a)
#define FFMA2(d, a, b) \
    asm("fma.rn.f32x2 %0, %1, %2, %0;" : "+l"(d) : "l"(a), "l"(b))
#define PACK2(d, lo, hi) \
    asm("mov.b64 %0, {%1, %2};" : "=l"(d) : "f"(lo), "f"(hi))
#define UNPACK2(lo, hi, d) \
    asm("mov.b64 {%0, %1}, %2;" : "=f"(lo), "=f"(hi) : "l"(d))

// fast exact-enough GELU: Abramowitz-Stegun 7.1.26 erf (|abs err| <= 1.5e-7)
__device__ __forceinline__ float gelu_f(float v) {
    const float xa = fabsf(v) * 0.70710678118654752f;
    const float t  = __fdividef(1.0f, fmaf(0.3275911f, xa, 1.0f));
    float poly = fmaf(t, 1.061405429f, -1.453152027f);
    poly = fmaf(t, poly, 1.421413741f);
    poly = fmaf(t, poly, -0.284496736f);
    poly = fmaf(t, poly, 0.254829592f);
    poly *= t;
    const float e = __expf(-xa * xa);
    float erfv = fmaf(-poly, e, 1.0f);
    erfv = copysignf(erfv, v);
    return 0.5f * v * (1.0f + erfv);
}

#define BARG(gid) asm volatile("bar.sync %0, 128;" :: "r"((gid) + 1) : "memory")

// ============================================================================
// Kernel PW (merged): blocks [0, 2025)  -> pack x[:, :128] + sincos passthru
//                     blocks [2025, 4050) -> wp[p][n][s] precompute
// ============================================================================
#define PACK_BLOCKS 2025   // 2025*256 = 16200*32 float4 slots
__global__ void __launch_bounds__(256) packwp_kernel(
    const float* __restrict__ x,
    const float* __restrict__ basis,
    const float* __restrict__ dw,
    float* __restrict__ out)
{
    const int t = threadIdx.x;

    if (blockIdx.x < PACK_BLOCKS) {
        // ---- pack role ----
        const int tid = blockIdx.x * 256 + t;
        {
            const int p = tid >> 5, c4 = tid & 31;
            const float* src = &x[p * MD + c4 * 4];
            *(float4*)&g_xL[p * L + c4 * 4] =
                make_float4(src[0], src[1], src[2], src[3]);
        }
        if (tid < P_TOT * 2) {
            const int p = tid >> 1, c = tid & 1;
            out[p * MD + L + c] = x[p * MD + L + c];
        }
        return;
    }

    // ---- wp role ----
    __shared__ __align__(16) float s_dw[S * K];
    for (int i = t; i < S * K; i += 256) s_dw[i] = dw[i];
    __syncthreads();

    const int pp = t >> 5, n = t & 31;
    const int p = (blockIdx.x - PACK_BLOCKS) * 8 + pp;
    if (n >= NNB) return;

    float b[K];
    #pragma unroll
    for (int k = 0; k < K; k++)
        b[k] = basis[(k * P_TOT + p) * NNB + n];

    float acc[S];
    #pragma unroll
    for (int s = 0; s < S; s++) {
        float a = 0.f;
        #pragma unroll
        for (int k = 0; k < K; k++)
            a = fmaf(s_dw[s * K + k], b[k], a);
        acc[s] = a;
    }
    float4* dst = (float4*)&g_wp[(p * NNB + n) * S];
    dst[0] = make_float4(acc[0],  acc[1],  acc[2],  acc[3]);
    dst[1] = make_float4(acc[4],  acc[5],  acc[6],  acc[7]);
    dst[2] = make_float4(acc[8],  acc[9],  acc[10], acc[11]);
    dst[3] = make_float4(acc[12], acc[13], acc[14], acc[15]);
}

// ============================================================================
// Kernel A: chunked register gather + double-buffered wp + heads -> g_xmix
//   f32x2 packed FMA core (R15 committed version, ~153us). FROZEN.
// ============================================================================
#define PPG 9
#define GCH 5   // gather chunk size (NNB = 5 chunks of 5)
__global__ void __launch_bounds__(256, 4) disco_heads_kernel(
    const int*   __restrict__ nbr,
    const float* __restrict__ db,
    const float* __restrict__ hw1,
    const float* __restrict__ hb1,
    const float* __restrict__ hw2,
    const float* __restrict__ hb2)
{
    __shared__ __align__(16) float s_db[S];
    __shared__ __align__(16) float s_w1[NH * S * MH];    // 16KB
    __shared__ __align__(16) float s_b1[NH * MH];
    __shared__ __align__(16) float s_w2[NH * MH];
    __shared__ __align__(16) float s_b2[NH];
    __shared__ __align__(16) float s_wp[2][2][NNB * S];  // [group][buf][n*16+s]
    __shared__ int s_nbrs[2][PPG * NNB];

    const int t  = threadIdx.x;
    const int g  = t >> 7;
    const int lt = t & 127;

    if (t < S) s_db[t] = db[t];
    for (int i = t; i < NH * S * MH; i += 256) s_w1[i] = hw1[i];
    for (int i = t; i < NH * MH; i += 256) { s_b1[i] = hb1[i]; s_w2[i] = hw2[i]; }
    if (t < NH) s_b2[t] = hb2[t];

    const int p0 = blockIdx.x * (2 * PPG) + g * PPG;
    for (int i = lt; i < PPG * NNB; i += 128)
        s_nbrs[g][i] = nbr[p0 * NNB + i];

    const int h = lt >> 4;
    const float4* wp4 = (const float4*)g_wp;

    // stage wp for pixel 0
    if (lt < 100)
        *(float4*)&s_wp[g][0][lt * 4] = wp4[p0 * 100 + lt];
    __syncthreads();

    for (int ip = 0; ip < PPG; ip++) {
        const int p = p0 + ip;
        const int buf = ip & 1;

        // prefetch next pixel's wp into the other buffer
        if (ip + 1 < PPG && lt < 100)
            *(float4*)&s_wp[g][buf ^ 1][lt * 4] = wp4[(p + 1) * 100 + lt];

        const int* nbp = &s_nbrs[g][ip * NNB];
        const float* wpb = s_wp[g][buf];

        // y accumulators: 8 packed pairs = y[0..15]
        u64 y2[8];
        {
            const u64* db2 = (const u64*)s_db;
            #pragma unroll
            for (int i = 0; i < 8; i++) y2[i] = db2[i];
        }

        // chunked gather (5x5) interleaved with y-loop
        #pragma unroll
        for (int ch = 0; ch < NNB / GCH; ch++) {
            float gv[GCH];
            #pragma unroll
            for (int j = 0; j < GCH; j++)
                gv[j] = __ldg(&g_xL[nbp[ch * GCH + j] * L + lt]);
            #pragma unroll
            for (int j = 0; j < GCH; j++) {
                const int n = ch * GCH + j;
                u64 gg; PACK2(gg, gv[j], gv[j]);
                const ulonglong2* wq = (const ulonglong2*)&wpb[n * S];
                const ulonglong2 wa = wq[0], wb = wq[1], wc = wq[2], wd = wq[3];
                FFMA2(y2[0], gg, wa.x); FFMA2(y2[1], gg, wa.y);
                FFMA2(y2[2], gg, wb.x); FFMA2(y2[3], gg, wb.y);
                FFMA2(y2[4], gg, wc.x); FFMA2(y2[5], gg, wc.y);
                FFMA2(y2[6], gg, wd.x); FFMA2(y2[7], gg, wd.y);
            }
        }
        float ys[16];
        #pragma unroll
        for (int i = 0; i < 8; i++) UNPACK2(ys[2*i], ys[2*i+1], y2[i]);

        // heads in two m-halves: h2[8] (16 regs) per half
        const float* w1h = &s_w1[h * S * MH];
        float hout = s_b2[h];
        #pragma unroll
        for (int half = 0; half < 2; half++) {
            const int mo = half * 16;   // m offset (floats)
            u64 h2[8];
            {
                const u64* b12 = (const u64*)&s_b1[h * MH + mo];
                #pragma unroll
                for (int j = 0; j < 8; j++) h2[j] = b12[j];
            }
            #pragma unroll
            for (int s = 0; s < 16; s++) {
                u64 yy; PACK2(yy, ys[s], ys[s]);
                const ulonglong2* wq = (const ulonglong2*)&w1h[s * MH + mo];
                #pragma unroll
                for (int c = 0; c < 4; c++) {
                    const ulonglong2 w = wq[c];
                    FFMA2(h2[2*c + 0], yy, w.x);
                    FFMA2(h2[2*c + 1], yy, w.y);
                }
            }
            u64 hacc = 0ULL;
            const u64* w22 = (const u64*)&s_w2[h * MH + mo];
            #pragma unroll
            for (int j = 0; j < 8; j++) {
                float f0, f1;
                UNPACK2(f0, f1, h2[j]);
                u64 gg; PACK2(gg, gelu_f(f0), gelu_f(f1));
                FFMA2(hacc, gg, w22[j]);
            }
            float e0, e1;
            UNPACK2(e0, e1, hacc);
            hout += e0 + e1;
        }

        g_xmix[p * L + lt] = hout + g_xL[p * L + lt];

        BARG(g);
    }
}

// ============================================================================
// Kernel F: fused FFN. phase1 frozen (R14); phase2 f32x2 with L-pairing
//   (weight pairs pre-packed from fw2 rows; hv packed once per (f,j)).
// ============================================================================
#define FP 24
#define XST2 26   // s_xT row stride (even -> u64-aligned pairs; conflict-free)
#define HFS 260   // padded hf row stride
__global__ void __launch_bounds__(256) ffn_kernel(
    const float* __restrict__ fw1,
    const float* __restrict__ fb1,
    const float* __restrict__ fw2,
    const float* __restrict__ fb2,
    float* __restrict__ out)
{
    __shared__ __align__(16) float s_xT[L * XST2];  // [d][pp] 13.3 KB
    __shared__ __align__(16) float s_hf[FP * HFS];  // [pp][f] 25.0 KB

    const int t = threadIdx.x;
    const int p0 = blockIdx.x * FP;

    // x tile transposed: thread (pp, c4) reads float4, scatters 4 rows
    {
        const float4* src = (const float4*)&g_xmix[p0 * L];
        #pragma unroll
        for (int i = t; i < FP * 32; i += 256) {
            const int pp = i >> 5, c4 = i & 31;
            const float4 v = src[i];
            s_xT[(c4 * 4 + 0) * XST2 + pp] = v.x;
            s_xT[(c4 * 4 + 1) * XST2 + pp] = v.y;
            s_xT[(c4 * 4 + 2) * XST2 + pp] = v.z;
            s_xT[(c4 * 4 + 3) * XST2 + pp] = v.w;
        }
    }
    __syncthreads();

    // phase 1: f4 = t>>2 (64 groups of 4 f), pq = t&3 (3 pixel-pairs each)
    {
        const int f4 = t >> 2, pq = t & 3;
        const float4 bb = *(const float4*)&fb1[f4 * 4];
        u64 acc0[3], acc1[3], acc2[3], acc3[3];
        #pragma unroll
        for (int j = 0; j < 3; j++) {
            PACK2(acc0[j], bb.x, bb.x);
            PACK2(acc1[j], bb.y, bb.y);
            PACK2(acc2[j], bb.z, bb.z);
            PACK2(acc3[j], bb.w, bb.w);
        }

        for (int d = 0; d < L; d++) {
            const float4 w = __ldg((const float4*)&fw1[d * FH + f4 * 4]);
            u64 w0, w1, w2, w3;
            PACK2(w0, w.x, w.x); PACK2(w1, w.y, w.y);
            PACK2(w2, w.z, w.z); PACK2(w3, w.w, w.w);
            const float* xrow = &s_xT[d * XST2 + pq * 6];
            #pragma unroll
            for (int j = 0; j < 3; j++) {
                const u64 xx = *(const u64*)&xrow[j * 2];
                FFMA2(acc0[j], xx, w0);
                FFMA2(acc1[j], xx, w1);
                FFMA2(acc2[j], xx, w2);
                FFMA2(acc3[j], xx, w3);
            }
        }
        #pragma unroll
        for (int j = 0; j < 3; j++) {
            float a0e, a0o, a1e, a1o, a2e, a2o, a3e, a3o;
            UNPACK2(a0e, a0o, acc0[j]);
            UNPACK2(a1e, a1o, acc1[j]);
            UNPACK2(a2e, a2o, acc2[j]);
            UNPACK2(a3e, a3o, acc3[j]);
            float4 he, ho;
            he.x = gelu_f(a0e); he.y = gelu_f(a1e);
            he.z = gelu_f(a2e); he.w = gelu_f(a3e);
            ho.x = gelu_f(a0o); ho.y = gelu_f(a1o);
            ho.z = gelu_f(a2o); ho.w = gelu_f(a3o);
            const int ppe = pq * 6 + j * 2;
            *(float4*)&s_hf[(ppe + 0) * HFS + f4 * 4] = he;
            *(float4*)&s_hf[(ppe + 1) * HFS + f4 * 4] = ho;
        }
    }
    __syncthreads();

    // phase 2: l4 = t>>3 (32 groups of 4 L), pg = t&7 (3 pixels each)
    //          f32x2 over adjacent L: weight pairs pre-packed via LDG.128
    {
        const int l4 = t >> 3, pg = t & 7;
        const ulonglong2 bb2 = *(const ulonglong2*)&fb2[l4 * 4];
        u64 a01[3], a23[3];
        #pragma unroll
        for (int j = 0; j < 3; j++) { a01[j] = bb2.x; a23[j] = bb2.y; }

        for (int f = 0; f < FH; f++) {
            const ulonglong2 w = __ldg((const ulonglong2*)&fw2[f * L + l4 * 4]);
            #pragma unroll
            for (int j = 0; j < 3; j++) {
                const float hv = s_hf[(pg * 3 + j) * HFS + f];
                u64 hh; PACK2(hh, hv, hv);
                FFMA2(a01[j], hh, w.x);
                FFMA2(a23[j], hh, w.y);
            }
        }
        #pragma unroll
        for (int j = 0; j < 3; j++) {
            const int pp = pg * 3 + j;
            const int p = p0 + pp;
            float f0, f1, f2, f3;
            UNPACK2(f0, f1, a01[j]);
            UNPACK2(f2, f3, a23[j]);
            float* o = &out[p * MD + l4 * 4];
            o[0] = f0 + s_xT[(l4 * 4 + 0) * XST2 + pp];
            o[1] = f1 + s_xT[(l4 * 4 + 1) * XST2 + pp];
            o[2] = f2 + s_xT[(l4 * 4 + 2) * XST2 + pp];
            o[3] = f3 + s_xT[(l4 * 4 + 3) * XST2 + pp];
        }
    }
}

// ============================================================================
// Launch
// ============================================================================
extern "C" void kernel_launch(void* const* d_in, const int* in_sizes, int n_in,
                              void* d_out, int out_size)
{
    const float* x     = (const float*)d_in[0];
    const int*   nbr   = (const int*)  d_in[1];
    const float* basis = (const float*)d_in[2];
    const float* dw    = (const float*)d_in[3];
    const float* db    = (const float*)d_in[4];
    const float* hw1   = (const float*)d_in[5];
    const float* hb1   = (const float*)d_in[6];
    const float* hw2   = (const float*)d_in[7];
    const float* hb2   = (const float*)d_in[8];
    const float* fw1   = (const float*)d_in[9];
    const float* fb1   = (const float*)d_in[10];
    const float* fw2   = (const float*)d_in[11];
    const float* fb2   = (const float*)d_in[12];
    float* out = (float*)d_out;

    packwp_kernel<<<PACK_BLOCKS + P_TOT / 8, 256>>>(x, basis, dw, out);
    disco_heads_kernel<<<P_TOT / (2 * PPG), 256>>>(nbr, db, hw1, hb1, hw2, hb2);
    ffn_kernel<<<P_TOT / FP, 256>>>(fw1, fb1, fw2, fb2, out);
}

// round 17
// speedup vs baseline: 1.0800x; 1.0800x over previous
#include <cuda_runtime.h>
#include <math.h>

// Problem constants
#define P_TOT   16200   // H*W
#define MD      130
#define L       128
#define NH      8
#define S       16
#define K       25
#define NNB     25
#define MH      32
#define FH      256

typedef unsigned long long u64;

// Scratch (allocation-free: __device__ globals)
__device__ __align__(16) float g_xL  [P_TOT * L];        // packed x[:, :128]
__device__ __align__(16) float g_wp  [P_TOT * NNB * S];  // precomputed W2
__device__ __align__(16) float g_xmix[P_TOT * L];        // x_mix

// packed f32x2 ops (sm_103a)
#define FFMA2(d, a, b) \
    asm("fma.rn.f32x2 %0, %1, %2, %0;" : "+l"(d) : "l"(a), "l"(b))
#define PACK2(d, lo, hi) \
    asm("mov.b64 %0, {%1, %2};" : "=l"(d) : "f"(lo), "f"(hi))
#define UNPACK2(lo, hi, d) \
    asm("mov.b64 {%0, %1}, %2;" : "=f"(lo), "=f"(hi) : "l"(d))

// fast exact-enough GELU: Abramowitz-Stegun 7.1.26 erf (|abs err| <= 1.5e-7)
__device__ __forceinline__ float gelu_f(float v) {
    const float xa = fabsf(v) * 0.70710678118654752f;
    const float t  = __fdividef(1.0f, fmaf(0.3275911f, xa, 1.0f));
    float poly = fmaf(t, 1.061405429f, -1.453152027f);
    poly = fmaf(t, poly, 1.421413741f);
    poly = fmaf(t, poly, -0.284496736f);
    poly = fmaf(t, poly, 0.254829592f);
    poly *= t;
    const float e = __expf(-xa * xa);
    float erfv = fmaf(-poly, e, 1.0f);
    erfv = copysignf(erfv, v);
    return 0.5f * v * (1.0f + erfv);
}

#define BARG(gid) asm volatile("bar.sync %0, 128;" :: "r"((gid) + 1) : "memory")

// ============================================================================
// Kernel X: pack x[:, :128] -> g_xL ; sincos -> out   (R15 version)
// ============================================================================
__global__ void __launch_bounds__(256) pack_kernel(
    const float* __restrict__ x, float* __restrict__ out)
{
    const int tid = blockIdx.x * 256 + threadIdx.x;
    if (tid < P_TOT * 32) {
        const int p = tid >> 5, c4 = tid & 31;
        const float* src = &x[p * MD + c4 * 4];
        *(float4*)&g_xL[p * L + c4 * 4] = make_float4(src[0], src[1], src[2], src[3]);
    }
    if (tid < P_TOT * 2) {
        const int p = tid >> 1, c = tid & 1;
        out[p * MD + L + c] = x[p * MD + L + c];
    }
}

// ============================================================================
// Kernel W: wp[p][n][s] = sum_k dw[s][k] * basis[k][p][n]   (R15 version)
// ============================================================================
__global__ void __launch_bounds__(256) wp_kernel(
    const float* __restrict__ basis,
    const float* __restrict__ dw)
{
    __shared__ __align__(16) float s_dw[S * K];
    const int t = threadIdx.x;
    for (int i = t; i < S * K; i += 256) s_dw[i] = dw[i];
    __syncthreads();

    const int pp = t >> 5, n = t & 31;
    const int p = blockIdx.x * 8 + pp;
    if (n >= NNB) return;

    float b[K];
    #pragma unroll
    for (int k = 0; k < K; k++)
        b[k] = basis[(k * P_TOT + p) * NNB + n];

    float acc[S];
    #pragma unroll
    for (int s = 0; s < S; s++) {
        float a = 0.f;
        #pragma unroll
        for (int k = 0; k < K; k++)
            a = fmaf(s_dw[s * K + k], b[k], a);
        acc[s] = a;
    }
    float4* dst = (float4*)&g_wp[(p * NNB + n) * S];
    dst[0] = make_float4(acc[0],  acc[1],  acc[2],  acc[3]);
    dst[1] = make_float4(acc[4],  acc[5],  acc[6],  acc[7]);
    dst[2] = make_float4(acc[8],  acc[9],  acc[10], acc[11]);
    dst[3] = make_float4(acc[12], acc[13], acc[14], acc[15]);
}

// ============================================================================
// Kernel A: chunked register gather + double-buffered wp + heads -> g_xmix
//   f32x2 packed FMA core; ysp broadcast pairs hoisted out of the m-halves.
// ============================================================================
#define PPG 9
#define GCH 5   // gather chunk size (NNB = 5 chunks of 5)
__global__ void __launch_bounds__(256, 4) disco_heads_kernel(
    const int*   __restrict__ nbr,
    const float* __restrict__ db,
    const float* __restrict__ hw1,
    const float* __restrict__ hb1,
    const float* __restrict__ hw2,
    const float* __restrict__ hb2)
{
    __shared__ __align__(16) float s_db[S];
    __shared__ __align__(16) float s_w1[NH * S * MH];    // 16KB
    __shared__ __align__(16) float s_b1[NH * MH];
    __shared__ __align__(16) float s_w2[NH * MH];
    __shared__ __align__(16) float s_b2[NH];
    __shared__ __align__(16) float s_wp[2][2][NNB * S];  // [group][buf][n*16+s]
    __shared__ int s_nbrs[2][PPG * NNB];

    const int t  = threadIdx.x;
    const int g  = t >> 7;
    const int lt = t & 127;

    if (t < S) s_db[t] = db[t];
    for (int i = t; i < NH * S * MH; i += 256) s_w1[i] = hw1[i];
    for (int i = t; i < NH * MH; i += 256) { s_b1[i] = hb1[i]; s_w2[i] = hw2[i]; }
    if (t < NH) s_b2[t] = hb2[t];

    const int p0 = blockIdx.x * (2 * PPG) + g * PPG;
    for (int i = lt; i < PPG * NNB; i += 128)
        s_nbrs[g][i] = nbr[p0 * NNB + i];

    const int h = lt >> 4;
    const float4* wp4 = (const float4*)g_wp;

    // stage wp for pixel 0
    if (lt < 100)
        *(float4*)&s_wp[g][0][lt * 4] = wp4[p0 * 100 + lt];
    __syncthreads();

    for (int ip = 0; ip < PPG; ip++) {
        const int p = p0 + ip;
        const int buf = ip & 1;

        // prefetch next pixel's wp into the other buffer
        if (ip + 1 < PPG && lt < 100)
            *(float4*)&s_wp[g][buf ^ 1][lt * 4] = wp4[(p + 1) * 100 + lt];

        const int* nbp = &s_nbrs[g][ip * NNB];
        const float* wpb = s_wp[g][buf];

        // y accumulators: 8 packed pairs = y[0..15]
        u64 y2[8];
        {
            const u64* db2 = (const u64*)s_db;
            #pragma unroll
            for (int i = 0; i < 8; i++) y2[i] = db2[i];
        }

        // chunked gather (5x5) interleaved with y-loop
        #pragma unroll
        for (int ch = 0; ch < NNB / GCH; ch++) {
            float gv[GCH];
            #pragma unroll
            for (int j = 0; j < GCH; j++)
                gv[j] = __ldg(&g_xL[nbp[ch * GCH + j] * L + lt]);
            #pragma unroll
            for (int j = 0; j < GCH; j++) {
                const int n = ch * GCH + j;
                u64 gg; PACK2(gg, gv[j], gv[j]);
                const ulonglong2* wq = (const ulonglong2*)&wpb[n * S];
                const ulonglong2 wa = wq[0], wb = wq[1], wc = wq[2], wd = wq[3];
                FFMA2(y2[0], gg, wa.x); FFMA2(y2[1], gg, wa.y);
                FFMA2(y2[2], gg, wb.x); FFMA2(y2[3], gg, wb.y);
                FFMA2(y2[4], gg, wc.x); FFMA2(y2[5], gg, wc.y);
                FFMA2(y2[6], gg, wd.x); FFMA2(y2[7], gg, wd.y);
            }
        }

        // broadcast pairs ysp[s] = {y[s], y[s]} hoisted (shared by both halves)
        u64 ysp[16];
        #pragma unroll
        for (int i = 0; i < 8; i++) {
            float f0, f1;
            UNPACK2(f0, f1, y2[i]);
            PACK2(ysp[2*i + 0], f0, f0);
            PACK2(ysp[2*i + 1], f1, f1);
        }

        // heads in two m-halves: h2[8] (16 regs) per half
        const float* w1h = &s_w1[h * S * MH];
        float hout = s_b2[h];
        #pragma unroll
        for (int half = 0; half < 2; half++) {
            const int mo = half * 16;   // m offset (floats)
            u64 h2[8];
            {
                const u64* b12 = (const u64*)&s_b1[h * MH + mo];
                #pragma unroll
                for (int j = 0; j < 8; j++) h2[j] = b12[j];
            }
            #pragma unroll
            for (int s = 0; s < 16; s++) {
                const u64 yy = ysp[s];
                const ulonglong2* wq = (const ulonglong2*)&w1h[s * MH + mo];
                #pragma unroll
                for (int c = 0; c < 4; c++) {
                    const ulonglong2 w = wq[c];
                    FFMA2(h2[2*c + 0], yy, w.x);
                    FFMA2(h2[2*c + 1], yy, w.y);
                }
            }
            u64 hacc = 0ULL;
            const u64* w22 = (const u64*)&s_w2[h * MH + mo];
            #pragma unroll
            for (int j = 0; j < 8; j++) {
                float f0, f1;
                UNPACK2(f0, f1, h2[j]);
                u64 gg; PACK2(gg, gelu_f(f0), gelu_f(f1));
                FFMA2(hacc, gg, w22[j]);
            }
            float e0, e1;
            UNPACK2(e0, e1, hacc);
            hout += e0 + e1;
        }

        g_xmix[p * L + lt] = hout + g_xL[p * L + lt];

        BARG(g);
    }
}

// ============================================================================
// Kernel F: fused FFN (R14/R15 committed version, measured 75.6-77.2us).
//   phase1 f32x2 pixel-pairs; phase2 scalar. FROZEN.
// ============================================================================
#define FP 24
#define XST2 26   // s_xT row stride (even -> u64-aligned pairs; conflict-free)
#define HFS 260   // padded hf row stride
__global__ void __launch_bounds__(256) ffn_kernel(
    const float* __restrict__ fw1,
    const float* __restrict__ fb1,
    const float* __restrict__ fw2,
    const float* __restrict__ fb2,
    float* __restrict__ out)
{
    __shared__ __align__(16) float s_xT[L * XST2];  // [d][pp] 13.3 KB
    __shared__ __align__(16) float s_hf[FP * HFS];  // [pp][f] 25.0 KB

    const int t = threadIdx.x;
    const int p0 = blockIdx.x * FP;

    // x tile transposed: thread (pp, c4) reads float4, scatters 4 rows
    {
        const float4* src = (const float4*)&g_xmix[p0 * L];
        #pragma unroll
        for (int i = t; i < FP * 32; i += 256) {
            const int pp = i >> 5, c4 = i & 31;
            const float4 v = src[i];
            s_xT[(c4 * 4 + 0) * XST2 + pp] = v.x;
            s_xT[(c4 * 4 + 1) * XST2 + pp] = v.y;
            s_xT[(c4 * 4 + 2) * XST2 + pp] = v.z;
            s_xT[(c4 * 4 + 3) * XST2 + pp] = v.w;
        }
    }
    __syncthreads();

    // phase 1: f4 = t>>2 (64 groups of 4 f), pq = t&3 (3 pixel-pairs each)
    {
        const int f4 = t >> 2, pq = t & 3;
        const float4 bb = *(const float4*)&fb1[f4 * 4];
        u64 acc0[3], acc1[3], acc2[3], acc3[3];
        #pragma unroll
        for (int j = 0; j < 3; j++) {
            PACK2(acc0[j], bb.x, bb.x);
            PACK2(acc1[j], bb.y, bb.y);
            PACK2(acc2[j], bb.z, bb.z);
            PACK2(acc3[j], bb.w, bb.w);
        }

        for (int d = 0; d < L; d++) {
            const float4 w = __ldg((const float4*)&fw1[d * FH + f4 * 4]);
            u64 w0, w1, w2, w3;
            PACK2(w0, w.x, w.x); PACK2(w1, w.y, w.y);
            PACK2(w2, w.z, w.z); PACK2(w3, w.w, w.w);
            const float* xrow = &s_xT[d * XST2 + pq * 6];
            #pragma unroll
            for (int j = 0; j < 3; j++) {
                const u64 xx = *(const u64*)&xrow[j * 2];
                FFMA2(acc0[j], xx, w0);
                FFMA2(acc1[j], xx, w1);
                FFMA2(acc2[j], xx, w2);
                FFMA2(acc3[j], xx, w3);
            }
        }
        #pragma unroll
        for (int j = 0; j < 3; j++) {
            float a0e, a0o, a1e, a1o, a2e, a2o, a3e, a3o;
            UNPACK2(a0e, a0o, acc0[j]);
            UNPACK2(a1e, a1o, acc1[j]);
            UNPACK2(a2e, a2o, acc2[j]);
            UNPACK2(a3e, a3o, acc3[j]);
            float4 he, ho;
            he.x = gelu_f(a0e); he.y = gelu_f(a1e);
            he.z = gelu_f(a2e); he.w = gelu_f(a3e);
            ho.x = gelu_f(a0o); ho.y = gelu_f(a1o);
            ho.z = gelu_f(a2o); ho.w = gelu_f(a3o);
            const int ppe = pq * 6 + j * 2;
            *(float4*)&s_hf[(ppe + 0) * HFS + f4 * 4] = he;
            *(float4*)&s_hf[(ppe + 1) * HFS + f4 * 4] = ho;
        }
    }
    __syncthreads();

    // phase 2: l4 = t>>3 (32 groups of 4 L), pg = t&7 (3 pixels each), scalar
    {
        const int l4 = t >> 3, pg = t & 7;
        const float4 bb = *(const float4*)&fb2[l4 * 4];
        float a0[3], a1[3], a2[3], a3[3];
        #pragma unroll
        for (int j = 0; j < 3; j++) { a0[j] = bb.x; a1[j] = bb.y; a2[j] = bb.z; a3[j] = bb.w; }

        for (int f = 0; f < FH; f++) {
            const float4 w = __ldg((const float4*)&fw2[f * L + l4 * 4]);
            #pragma unroll
            for (int j = 0; j < 3; j++) {
                const float hv = s_hf[(pg * 3 + j) * HFS + f];
                a0[j] = fmaf(hv, w.x, a0[j]);
                a1[j] = fmaf(hv, w.y, a1[j]);
                a2[j] = fmaf(hv, w.z, a2[j]);
                a3[j] = fmaf(hv, w.w, a3[j]);
            }
        }
        #pragma unroll
        for (int j = 0; j < 3; j++) {
            const int pp = pg * 3 + j;
            const int p = p0 + pp;
            float* o = &out[p * MD + l4 * 4];
            o[0] = a0[j] + s_xT[(l4 * 4 + 0) * XST2 + pp];
            o[1] = a1[j] + s_xT[(l4 * 4 + 1) * XST2 + pp];
            o[2] = a2[j] + s_xT[(l4 * 4 + 2) * XST2 + pp];
            o[3] = a3[j] + s_xT[(l4 * 4 + 3) * XST2 + pp];
        }
    }
}

// ============================================================================
// Launch
// ============================================================================
extern "C" void kernel_launch(void* const* d_in, const int* in_sizes, int n_in,
                              void* d_out, int out_size)
{
    const float* x     = (const float*)d_in[0];
    const int*   nbr   = (const int*)  d_in[1];
    const float* basis = (const float*)d_in[2];
    const float* dw    = (const float*)d_in[3];
    const float* db    = (const float*)d_in[4];
    const float* hw1   = (const float*)d_in[5];
    const float* hb1   = (const float*)d_in[6];
    const float* hw2   = (const float*)d_in[7];
    const float* hb2   = (const float*)d_in[8];
    const float* fw1   = (const float*)d_in[9];
    const float* fb1   = (const float*)d_in[10];
    const float* fw2   = (const float*)d_in[11];
    const float* fb2   = (const float*)d_in[12];
    float* out = (float*)d_out;

    pack_kernel<<<(P_TOT * 32 + 255) / 256, 256>>>(x, out);
    wp_kernel<<<P_TOT / 8, 256>>>(basis, dw);
    disco_heads_kernel<<<P_TOT / (2 * PPG), 256>>>(nbr, db, hw1, hb1, hw2, hb2);
    ffn_kernel<<<P_TOT / FP, 256>>>(fw1, fb1, fw2, fb2, out);
}